// round 4
// baseline (speedup 1.0000x reference)
#include <cuda_runtime.h>
#include <cuda_fp16.h>

// int4-quantized GEMV, QB=128. Harness passes fp16 tensors upcast to fp32:
//   d_in[0] x       : float[K]        (K = 8192)
//   d_in[1] packed_w: int32[N, K/2]   (one byte of two nibbles per int32)
//   d_in[2] scales  : float[N, K/QB]
//   d_out  out      : float[N]
//
// Fast path: warp-per-row, 8 rows/block. x staged into SMEM as half2
// (lossless: data originated as fp16; gives conflict-free LDS.128).
// Nibbles -> fp16 via 0x6400 exponent trick (no I2F), fp32 accumulation,
// one scale FMA per 8-weight chunk (8 | 128 so chunks never straddle blocks).

#define FAST_K 8192

__global__ void __launch_bounds__(256, 1)
q4gemv_fast(const float* __restrict__ x,
            const int*   __restrict__ pw,
            const float* __restrict__ scales,
            float*       __restrict__ out,
            int N)
{
    __shared__ __half xs[FAST_K];                 // 16 KB

    const int tid = threadIdx.x;

    // Stage x: read fp32, convert (losslessly) to fp16 pairs in SMEM.
    {
        const float4* xsrc = reinterpret_cast<const float4*>(x);
        uint2*        xdst = reinterpret_cast<uint2*>(xs);
        #pragma unroll
        for (int i = 0; i < (FAST_K / 4) / 256; ++i) {   // 2048/256 = 8
            const int idx = tid + i * 256;
            float4 v = xsrc[idx];
            __half2 a = __floats2half2_rn(v.x, v.y);
            __half2 b = __floats2half2_rn(v.z, v.w);
            uint2 u;
            u.x = *reinterpret_cast<unsigned*>(&a);
            u.y = *reinterpret_cast<unsigned*>(&b);
            xdst[idx] = u;
        }
    }
    __syncthreads();

    const int warp = tid >> 5;
    const int lane = tid & 31;
    const int row  = blockIdx.x * 8 + warp;
    if (row >= N) return;

    // Preload this row's 64 scales: lane l holds scales[2l], scales[2l+1].
    const float s0 = scales[(size_t)row * 64 + 2 * lane];
    const float s1 = scales[(size_t)row * 64 + 2 * lane + 1];

    const uint4* prow = reinterpret_cast<const uint4*>(pw) + (size_t)row * (FAST_K / 8);
    const uint4* xsv  = reinterpret_cast<const uint4*>(xs);

    const unsigned off_bits = 0x64086408u;        // half2(1032, 1032)
    const __half2 off = *reinterpret_cast<const __half2*>(&off_bits);

    float acc = 0.0f;

    #pragma unroll 4
    for (int it = 0; it < 32; ++it) {
        const int c = it * 32 + lane;             // 8-weight chunk index 0..1023
        uint4 w  = prow[c];                       // 4 int32 (one nibble-pair each... x4)
        uint4 xv = xsv[c];                        // x[8c..8c+8) as 4x half2

        // Quant block of this chunk = c>>4 = it*2 + (lane>>4).
        // Lane `it` holds scales (2it, 2it+1); pick by lane>=16.
        float sa = __shfl_sync(0xffffffffu, s0, it);
        float sb = __shfl_sync(0xffffffffu, s1, it);
        float s  = (lane & 16) ? sb : sa;

        float p = 0.0f;
        #pragma unroll
        for (int j = 0; j < 4; ++j) {
            unsigned b = reinterpret_cast<const unsigned*>(&w)[j];
            // half2(1024+lo, 1024+hi), exact subtract 1032 -> (lo-8, hi-8)
            unsigned t = ((b | (b << 12)) & 0x000F000Fu) | 0x64006400u;
            __half2 w2 = __hsub2(*reinterpret_cast<const __half2*>(&t), off);
            float2 wf = __half22float2(w2);
            float2 xf = __half22float2(reinterpret_cast<const __half2*>(&xv)[j]);
            p = fmaf(wf.x, xf.x, p);
            p = fmaf(wf.y, xf.y, p);
        }
        acc = fmaf(p, s, acc);
    }

    // Warp reduction
    #pragma unroll
    for (int o = 16; o; o >>= 1)
        acc += __shfl_xor_sync(0xffffffffu, acc, o);

    if (lane == 0)
        out[row] = acc;
}

// Generic fallback (any K / QB / N), fp32 in/out. Slow but correct.
__global__ void q4gemv_generic(const float* __restrict__ x,
                               const int*   __restrict__ pw,
                               const float* __restrict__ scales,
                               float*       __restrict__ out,
                               int N, int K, int QB)
{
    int row = blockIdx.x * blockDim.x + threadIdx.x;
    if (row >= N) return;
    const int halfK = K / 2;
    const int nblk  = K / QB;
    const int ipb   = QB / 2;     // int32s per quant block
    float acc = 0.0f;
    for (int blk = 0; blk < nblk; ++blk) {
        float p = 0.0f;
        for (int i = 0; i < ipb; ++i) {
            int idx = blk * ipb + i;
            unsigned b = (unsigned)pw[(size_t)row * halfK + idx];
            float lo = (float)(int)(b & 15u) - 8.0f;
            float hi = (float)(int)((b >> 4) & 15u) - 8.0f;
            p = fmaf(lo, x[2 * idx],     p);
            p = fmaf(hi, x[2 * idx + 1], p);
        }
        acc = fmaf(p, scales[(size_t)row * nblk + blk], acc);
    }
    out[row] = acc;
}

extern "C" void kernel_launch(void* const* d_in, const int* in_sizes, int n_in,
                              void* d_out, int out_size)
{
    const float* x  = (const float*)d_in[0];
    const int*   pw = (const int*)  d_in[1];
    const float* sc = (const float*)d_in[2];
    float*       out = (float*)d_out;

    const long long K_ll = in_sizes[0];
    const int K  = (int)K_ll;
    const int N  = (int)(((long long)in_sizes[1] * 2) / K_ll);
    const int QB = (int)(((long long)N * K_ll) / in_sizes[2]);

    if (K == FAST_K && QB == 128 && (N % 8) == 0) {
        q4gemv_fast<<<N / 8, 256>>>(x, pw, sc, out, N);
    } else {
        int threads = 256;
        int blocks = (N + threads - 1) / threads;
        q4gemv_generic<<<blocks, threads>>>(x, pw, sc, out, N, K, QB);
    }
}

// round 5
// speedup vs baseline: 1.0643x; 1.0643x over previous
#include <cuda_runtime.h>
#include <cuda_fp16.h>

// int4-quantized GEMV, QB=128, K=8192. fp16 tensors arrive upcast to fp32.
//   d_in[0] x       : float[8192]
//   d_in[1] packed_w: int32[N, 4096]  (low/high nibble per int32, offset-8)
//   d_in[2] scales  : float[N, 64]
//   d_out  out      : float[N]
//
// R4: 2 rows per warp (16 rows/block, grid=N/16=512 -> single wave at 4
// blocks/SM), scales via SMEM broadcast instead of shuffles, __ldcs streaming
// loads for weights, x staged once per block as half2 (lossless, conflict-free
// LDS.128). fp32 accumulation.

#define FAST_K 8192

__global__ void __launch_bounds__(256, 4)
q4gemv_fast2(const float* __restrict__ x,
             const int*   __restrict__ pw,
             const float* __restrict__ scales,
             float*       __restrict__ out,
             int N)
{
    __shared__ __half xs[FAST_K];        // 16 KB
    __shared__ float  scsm[16 * 64];     // 4 KB: 16 rows x 64 block-scales

    const int tid  = threadIdx.x;
    const int base = blockIdx.x * 16;    // first row of this block

    // Stage x: fp32 -> fp16 (lossless; source data originated as fp16).
    {
        const float4* xsrc = reinterpret_cast<const float4*>(x);
        uint2*        xdst = reinterpret_cast<uint2*>(xs);
        #pragma unroll
        for (int i = 0; i < (FAST_K / 4) / 256; ++i) {   // 8 iters
            const int idx = tid + i * 256;
            float4 v = xsrc[idx];
            __half2 a = __floats2half2_rn(v.x, v.y);
            __half2 b = __floats2half2_rn(v.z, v.w);
            uint2 u;
            u.x = *reinterpret_cast<unsigned*>(&a);
            u.y = *reinterpret_cast<unsigned*>(&b);
            xdst[idx] = u;
        }
    }
    // Stage this block's 16x64 scales.
    {
        #pragma unroll
        for (int i = 0; i < 4; ++i) {
            const int idx = tid + i * 256;            // 0..1023
            scsm[idx] = scales[(size_t)(base + (idx >> 6)) * 64 + (idx & 63)];
        }
    }
    __syncthreads();

    const int warp = tid >> 5;
    const int lane = tid & 31;
    const int r0   = base + warp * 2;                 // this warp's two rows

    const uint4* prow0 = reinterpret_cast<const uint4*>(pw) + (size_t)r0 * (FAST_K / 8);
    const uint4* prow1 = prow0 + (FAST_K / 8);
    const uint4* xsv   = reinterpret_cast<const uint4*>(xs);
    const float* sc0   = scsm + (warp * 2)     * 64;
    const float* sc1   = scsm + (warp * 2 + 1) * 64;

    const unsigned off_bits = 0x64086408u;            // half2(1032, 1032)
    const __half2 off = *reinterpret_cast<const __half2*>(&off_bits);

    float acc0 = 0.0f, acc1 = 0.0f;

    #pragma unroll 2
    for (int it = 0; it < 32; ++it) {
        const int c = it * 32 + lane;                 // 8-weight chunk 0..1023
        uint4 w0 = __ldcs(prow0 + c);                 // streaming: don't pollute L2
        uint4 w1 = __ldcs(prow1 + c);
        uint4 xv = xsv[c];

        // Quant block of this chunk = c >> 4 = 2*it + (lane>=16).
        const int col = 2 * it + (lane >> 4);         // 2 addrs/warp -> smem broadcast
        const float s0 = sc0[col];
        const float s1 = sc1[col];

        float p0 = 0.0f, p1 = 0.0f;
        #pragma unroll
        for (int j = 0; j < 4; ++j) {
            const unsigned b0 = reinterpret_cast<const unsigned*>(&w0)[j];
            const unsigned b1 = reinterpret_cast<const unsigned*>(&w1)[j];
            float2 xf = __half22float2(reinterpret_cast<const __half2*>(&xv)[j]);

            unsigned t0 = ((b0 | (b0 << 12)) & 0x000F000Fu) | 0x64006400u;
            __half2 h0 = __hsub2(*reinterpret_cast<const __half2*>(&t0), off);
            float2 wf0 = __half22float2(h0);
            p0 = fmaf(wf0.x, xf.x, p0);
            p0 = fmaf(wf0.y, xf.y, p0);

            unsigned t1 = ((b1 | (b1 << 12)) & 0x000F000Fu) | 0x64006400u;
            __half2 h1 = __hsub2(*reinterpret_cast<const __half2*>(&t1), off);
            float2 wf1 = __half22float2(h1);
            p1 = fmaf(wf1.x, xf.x, p1);
            p1 = fmaf(wf1.y, xf.y, p1);
        }
        acc0 = fmaf(p0, s0, acc0);
        acc1 = fmaf(p1, s1, acc1);
    }

    // Warp reductions (two values).
    #pragma unroll
    for (int o = 16; o; o >>= 1) {
        acc0 += __shfl_xor_sync(0xffffffffu, acc0, o);
        acc1 += __shfl_xor_sync(0xffffffffu, acc1, o);
    }

    if (lane == 0) {
        out[r0]     = acc0;
        out[r0 + 1] = acc1;
    }
}

// Generic fallback (any K / QB / N), fp32 in/out.
__global__ void q4gemv_generic(const float* __restrict__ x,
                               const int*   __restrict__ pw,
                               const float* __restrict__ scales,
                               float*       __restrict__ out,
                               int N, int K, int QB)
{
    int row = blockIdx.x * blockDim.x + threadIdx.x;
    if (row >= N) return;
    const int halfK = K / 2;
    const int nblk  = K / QB;
    const int ipb   = QB / 2;
    float acc = 0.0f;
    for (int blk = 0; blk < nblk; ++blk) {
        float p = 0.0f;
        for (int i = 0; i < ipb; ++i) {
            int idx = blk * ipb + i;
            unsigned b = (unsigned)pw[(size_t)row * halfK + idx];
            float lo = (float)(int)(b & 15u) - 8.0f;
            float hi = (float)(int)((b >> 4) & 15u) - 8.0f;
            p = fmaf(lo, x[2 * idx],     p);
            p = fmaf(hi, x[2 * idx + 1], p);
        }
        acc = fmaf(p, scales[(size_t)row * nblk + blk], acc);
    }
    out[row] = acc;
}

extern "C" void kernel_launch(void* const* d_in, const int* in_sizes, int n_in,
                              void* d_out, int out_size)
{
    const float* x  = (const float*)d_in[0];
    const int*   pw = (const int*)  d_in[1];
    const float* sc = (const float*)d_in[2];
    float*       out = (float*)d_out;

    const long long K_ll = in_sizes[0];
    const int K  = (int)K_ll;
    const int N  = (int)(((long long)in_sizes[1] * 2) / K_ll);
    const int QB = (int)(((long long)N * K_ll) / in_sizes[2]);

    if (K == FAST_K && QB == 128 && (N % 16) == 0) {
        q4gemv_fast2<<<N / 16, 256>>>(x, pw, sc, out, N);
    } else {
        int threads = 256;
        int blocks = (N + threads - 1) / threads;
        q4gemv_generic<<<blocks, threads>>>(x, pw, sc, out, N, K, QB);
    }
}